// round 12
// baseline (speedup 1.0000x reference)
#include <cuda_runtime.h>
#include <math.h>

#define S_LEN   2048
#define HID     2048
#define NH      16
#define NKV     4
#define HD      128
#define HEAVY   204
#define RECENT  204
#define QKV_N   3072
#define SCALE   0.08838834764831845f   // 1/sqrt(128)

// ---------------- scratch (__device__ globals; no allocation allowed) -------
__device__ float g_qkv[S_LEN * QKV_N];                    // [s][3072] q|k|v pre-rope
__device__ float g_q[NH * S_LEN * HD];                    // [h][s][d] post-rope
__device__ float g_k[NKV * S_LEN * HD];                   // [kv][s][d] post-rope
__device__ float g_v[NKV * S_LEN * HD];                   // [kv][s][d]
__device__ float g_scores[(size_t)NH * S_LEN * S_LEN];    // [h][i][j], lower triangle valid
__device__ float g_rowmax[NH * S_LEN];
__device__ float g_colsum[NH * S_LEN];
__device__ int   g_heavy[NH * HEAVY];
__device__ float g_attn[S_LEN * HID];                     // [i][h*128+d]

// ---------------- fused QKV projection: hidden @ {Wq,Wk,Wv} + bias ----------
// 128x128 tile, BK=8, 256 threads, 8x8 per thread.
__global__ void __launch_bounds__(256) qkv_gemm(
    const float* __restrict__ A,
    const float* __restrict__ Wq, const float* __restrict__ bq,
    const float* __restrict__ Wk, const float* __restrict__ bk,
    const float* __restrict__ Wv, const float* __restrict__ bv)
{
    __shared__ float As[8][128];
    __shared__ float Bs[8][128];

    int cb = blockIdx.x;               // 0..23 (16 q-blocks, 4 k, 4 v)
    int rb = blockIdx.y;               // 0..15
    const float* W; const float* bias; int ldw; int ncol0;
    if (cb < 16)      { W = Wq; bias = bq; ldw = 2048; ncol0 = cb * 128; }
    else if (cb < 20) { W = Wk; bias = bk; ldw = 512;  ncol0 = (cb - 16) * 128; }
    else              { W = Wv; bias = bv; ldw = 512;  ncol0 = (cb - 20) * 128; }

    int tid  = threadIdx.x;
    int aRow = tid >> 1;               // 0..127
    int aCol = (tid & 1) * 4;          // 0 or 4
    int bRow = tid >> 5;               // 0..7
    int bCol = (tid & 31) * 4;         // 0..124
    int tx = tid & 15, ty = tid >> 4;

    const float* Ab = A + (size_t)(rb * 128 + aRow) * 2048 + aCol;
    const float* Bb = W + (size_t)bRow * ldw + ncol0 + bCol;

    float acc[8][8];
#pragma unroll
    for (int r = 0; r < 8; r++)
#pragma unroll
        for (int c = 0; c < 8; c++) acc[r][c] = 0.f;

    for (int k0 = 0; k0 < 2048; k0 += 8) {
        float4 a4 = *(const float4*)(Ab + k0);
        As[aCol + 0][aRow] = a4.x;
        As[aCol + 1][aRow] = a4.y;
        As[aCol + 2][aRow] = a4.z;
        As[aCol + 3][aRow] = a4.w;
        float4 b4 = *(const float4*)(Bb + (size_t)k0 * ldw);
        *(float4*)&Bs[bRow][bCol] = b4;
        __syncthreads();
#pragma unroll
        for (int kk = 0; kk < 8; kk++) {
            float4 a0 = *(const float4*)&As[kk][ty * 8];
            float4 a1 = *(const float4*)&As[kk][ty * 8 + 4];
            float4 b0 = *(const float4*)&Bs[kk][tx * 8];
            float4 b1 = *(const float4*)&Bs[kk][tx * 8 + 4];
            float ar[8] = {a0.x, a0.y, a0.z, a0.w, a1.x, a1.y, a1.z, a1.w};
            float br[8] = {b0.x, b0.y, b0.z, b0.w, b1.x, b1.y, b1.z, b1.w};
#pragma unroll
            for (int r = 0; r < 8; r++)
#pragma unroll
                for (int c = 0; c < 8; c++)
                    acc[r][c] = fmaf(ar[r], br[c], acc[r][c]);
        }
        __syncthreads();
    }
#pragma unroll
    for (int r = 0; r < 8; r++) {
        int grow = rb * 128 + ty * 8 + r;
        float* Crow = g_qkv + (size_t)grow * QKV_N + cb * 128 + tx * 8;
#pragma unroll
        for (int c = 0; c < 8; c++)
            Crow[c] = acc[r][c] + bias[ncol0 + tx * 8 + c];
    }
}

// ---------------- RoPE + split into head-major layouts ----------------------
__global__ void rope_kernel(const float* __restrict__ cosb,
                            const float* __restrict__ sinb)
{
    int idx = blockIdx.x * 256 + threadIdx.x;
    if (idx >= S_LEN * QKV_N) return;
    int s = idx / QKV_N;
    int c = idx % QKV_N;
    float x = g_qkv[idx];
    if (c < 2048) {                              // Q heads
        int h = c >> 7, d = c & 127;
        float cs = cosb[s * HD + d], sn = sinb[s * HD + d];
        float rot = (d < 64) ? -g_qkv[(size_t)s * QKV_N + c + 64]
                             :  g_qkv[(size_t)s * QKV_N + c - 64];
        g_q[((size_t)h * S_LEN + s) * HD + d] = x * cs + rot * sn;
    } else if (c < 2560) {                       // K heads
        int kc = c - 2048;
        int kv = kc >> 7, d = kc & 127;
        float cs = cosb[s * HD + d], sn = sinb[s * HD + d];
        float rot = (d < 64) ? -g_qkv[(size_t)s * QKV_N + c + 64]
                             :  g_qkv[(size_t)s * QKV_N + c - 64];
        g_k[((size_t)kv * S_LEN + s) * HD + d] = x * cs + rot * sn;
    } else {                                     // V heads (no rope)
        int vc = c - 2560;
        int kv = vc >> 7, d = vc & 127;
        g_v[((size_t)kv * S_LEN + s) * HD + d] = x;
    }
}

// ---------------- scores = scale * q @ k^T (lower-triangle tiles only) ------
__global__ void __launch_bounds__(256) scores_gemm()
{
    int jt = blockIdx.x, it = blockIdx.y, h = blockIdx.z;
    if (jt > it) return;

    __shared__ float As[8][128];
    __shared__ float Bs[8][128];

    const float* Q  = g_q + (size_t)h * S_LEN * HD;
    const float* Kk = g_k + (size_t)(h >> 2) * S_LEN * HD;

    int tid  = threadIdx.x;
    int aRow = tid >> 1;
    int aCol = (tid & 1) * 4;
    int tx = tid & 15, ty = tid >> 4;

    const float* Ab = Q  + (size_t)(it * 128 + aRow) * HD + aCol;
    const float* Bb = Kk + (size_t)(jt * 128 + aRow) * HD + aCol;

    float acc[8][8];
#pragma unroll
    for (int r = 0; r < 8; r++)
#pragma unroll
        for (int c = 0; c < 8; c++) acc[r][c] = 0.f;

    for (int k0 = 0; k0 < HD; k0 += 8) {
        float4 a4 = *(const float4*)(Ab + k0);
        As[aCol + 0][aRow] = a4.x;
        As[aCol + 1][aRow] = a4.y;
        As[aCol + 2][aRow] = a4.z;
        As[aCol + 3][aRow] = a4.w;
        float4 b4 = *(const float4*)(Bb + k0);
        Bs[aCol + 0][aRow] = b4.x;
        Bs[aCol + 1][aRow] = b4.y;
        Bs[aCol + 2][aRow] = b4.z;
        Bs[aCol + 3][aRow] = b4.w;
        __syncthreads();
#pragma unroll
        for (int kk = 0; kk < 8; kk++) {
            float4 a0 = *(const float4*)&As[kk][ty * 8];
            float4 a1 = *(const float4*)&As[kk][ty * 8 + 4];
            float4 b0 = *(const float4*)&Bs[kk][tx * 8];
            float4 b1 = *(const float4*)&Bs[kk][tx * 8 + 4];
            float ar[8] = {a0.x, a0.y, a0.z, a0.w, a1.x, a1.y, a1.z, a1.w};
            float br[8] = {b0.x, b0.y, b0.z, b0.w, b1.x, b1.y, b1.z, b1.w};
#pragma unroll
            for (int r = 0; r < 8; r++)
#pragma unroll
                for (int c = 0; c < 8; c++)
                    acc[r][c] = fmaf(ar[r], br[c], acc[r][c]);
        }
        __syncthreads();
    }
#pragma unroll
    for (int r = 0; r < 8; r++) {
        size_t row = (size_t)h * S_LEN + it * 128 + ty * 8 + r;
        float* Crow = g_scores + row * S_LEN + jt * 128 + tx * 8;
#pragma unroll
        for (int c = 0; c < 8; c++)
            Crow[c] = acc[r][c] * SCALE;
    }
}

// ---------------- zero colsum ------------------------------------------------
__global__ void zero_colsum()
{
    int idx = blockIdx.x * 256 + threadIdx.x;
    if (idx < NH * S_LEN) g_colsum[idx] = 0.f;
}

// ---------------- per-row softmax stats + colsum accumulation ---------------
// One block per (i, h). Causal: only j <= i valid.
__global__ void __launch_bounds__(256) row_softmax_colsum_kernel()
{
    int i = blockIdx.x, h = blockIdx.y;
    int tid = threadIdx.x;
    const float* srow = g_scores + ((size_t)h * S_LEN + i) * S_LEN;
    int L = i + 1;

    __shared__ float sh[S_LEN];
    __shared__ float red[256];

    float mloc = -3.4e38f;
    for (int j = tid; j < L; j += 256) {
        float v = srow[j];
        sh[j] = v;
        mloc = fmaxf(mloc, v);
    }
    red[tid] = mloc;
    __syncthreads();
    for (int s2 = 128; s2 > 0; s2 >>= 1) {
        if (tid < s2) red[tid] = fmaxf(red[tid], red[tid + s2]);
        __syncthreads();
    }
    float m = red[0];
    __syncthreads();

    float ssum = 0.f;
    for (int j = tid; j < L; j += 256) {
        float e = expf(sh[j] - m);
        sh[j] = e;
        ssum += e;
    }
    red[tid] = ssum;
    __syncthreads();
    for (int s2 = 128; s2 > 0; s2 >>= 1) {
        if (tid < s2) red[tid] += red[tid + s2];
        __syncthreads();
    }
    float inv = 1.0f / red[0];
    if (tid == 0) g_rowmax[h * S_LEN + i] = m;

    for (int j = tid; j < L; j += 256)
        atomicAdd(&g_colsum[h * S_LEN + j], sh[j] * inv);
}

// ---------------- per-head top-k (iterative argmax, lower-index tiebreak) ---
__global__ void __launch_bounds__(256) topk_kernel()
{
    int h = blockIdx.x;
    int tid = threadIdx.x;
    __shared__ float vals[S_LEN];
    __shared__ float rv[256];
    __shared__ int   ri[256];

    for (int j = tid; j < S_LEN; j += 256) vals[j] = g_colsum[h * S_LEN + j];
    __syncthreads();

    for (int t = 0; t < HEAVY; t++) {
        float bv = -3.4e38f; int bi = S_LEN;
        for (int j = tid; j < S_LEN; j += 256) {
            float v = vals[j];
            if (v > bv || (v == bv && j < bi)) { bv = v; bi = j; }
        }
        rv[tid] = bv; ri[tid] = bi;
        __syncthreads();
        for (int s2 = 128; s2 > 0; s2 >>= 1) {
            if (tid < s2) {
                float v2 = rv[tid + s2]; int i2 = ri[tid + s2];
                if (v2 > rv[tid] || (v2 == rv[tid] && i2 < ri[tid])) {
                    rv[tid] = v2; ri[tid] = i2;
                }
            }
            __syncthreads();
        }
        if (tid == 0) {
            int sel = ri[0];
            g_heavy[h * HEAVY + t] = sel;
            vals[sel] = -3.4e38f;
        }
        __syncthreads();
    }
}

// ---------------- masked softmax * V (sparse over kept columns) -------------
// keep(j) = |i-j|<=RECENT (causal => j in [i-RECENT, i])  OR  heavy j with j < i-RECENT.
// Uses full-row max m_i (kept-max <= m_i, ratios unchanged).
__global__ void __launch_bounds__(128) attn_v_kernel()
{
    int i = blockIdx.x, h = blockIdx.y;
    int d = threadIdx.x;                 // 0..127
    int kv = h >> 2;

    const float* srow = g_scores + ((size_t)h * S_LEN + i) * S_LEN;
    const float* V = g_v + (size_t)kv * S_LEN * HD;
    float m = g_rowmax[h * S_LEN + i];

    __shared__ float w[128];
    __shared__ int   jidx[128];

    float acc = 0.f, wsum = 0.f;

    // recent band: j in [max(0, i-RECENT), i]
    int rlo = i - RECENT; if (rlo < 0) rlo = 0;
    for (int base = rlo; base <= i; base += 128) {
        int cnt = i - base + 1; if (cnt > 128) cnt = 128;
        if (d < cnt) w[d] = expf(srow[base + d] - m);
        __syncthreads();
        for (int t = 0; t < cnt; t++) {
            float ww = w[t];
            wsum += ww;
            acc = fmaf(ww, V[(size_t)(base + t) * HD + d], acc);
        }
        __syncthreads();
    }

    // heavy-only columns: j < i - RECENT
    int cutoff = i - RECENT;
    for (int base = 0; base < HEAVY; base += 128) {
        int cnt = HEAVY - base; if (cnt > 128) cnt = 128;
        if (d < cnt) {
            int j = g_heavy[h * HEAVY + base + d];
            if (j < cutoff) { jidx[d] = j; w[d] = expf(srow[j] - m); }
            else            { jidx[d] = -1; w[d] = 0.f; }
        }
        __syncthreads();
        for (int t = 0; t < cnt; t++) {
            int j = jidx[t];
            if (j >= 0) {
                float ww = w[t];
                wsum += ww;
                acc = fmaf(ww, V[(size_t)j * HD + d], acc);
            }
        }
        __syncthreads();
    }

    g_attn[(size_t)i * HID + h * HD + d] = acc / wsum;
}

// ---------------- output projection: attn @ Wo -------------------------------
__global__ void __launch_bounds__(256) out_gemm(const float* __restrict__ W,
                                                float* __restrict__ C)
{
    __shared__ float As[8][128];
    __shared__ float Bs[8][128];

    int cb = blockIdx.x, rb = blockIdx.y;
    int tid  = threadIdx.x;
    int aRow = tid >> 1;
    int aCol = (tid & 1) * 4;
    int bRow = tid >> 5;
    int bCol = (tid & 31) * 4;
    int tx = tid & 15, ty = tid >> 4;

    const float* Ab = g_attn + (size_t)(rb * 128 + aRow) * HID + aCol;
    const float* Bb = W + (size_t)bRow * HID + cb * 128 + bCol;

    float acc[8][8];
#pragma unroll
    for (int r = 0; r < 8; r++)
#pragma unroll
        for (int c = 0; c < 8; c++) acc[r][c] = 0.f;

    for (int k0 = 0; k0 < HID; k0 += 8) {
        float4 a4 = *(const float4*)(Ab + k0);
        As[aCol + 0][aRow] = a4.x;
        As[aCol + 1][aRow] = a4.y;
        As[aCol + 2][aRow] = a4.z;
        As[aCol + 3][aRow] = a4.w;
        float4 b4 = *(const float4*)(Bb + (size_t)k0 * HID);
        *(float4*)&Bs[bRow][bCol] = b4;
        __syncthreads();
#pragma unroll
        for (int kk = 0; kk < 8; kk++) {
            float4 a0 = *(const float4*)&As[kk][ty * 8];
            float4 a1 = *(const float4*)&As[kk][ty * 8 + 4];
            float4 b0 = *(const float4*)&Bs[kk][tx * 8];
            float4 b1 = *(const float4*)&Bs[kk][tx * 8 + 4];
            float ar[8] = {a0.x, a0.y, a0.z, a0.w, a1.x, a1.y, a1.z, a1.w};
            float br[8] = {b0.x, b0.y, b0.z, b0.w, b1.x, b1.y, b1.z, b1.w};
#pragma unroll
            for (int r = 0; r < 8; r++)
#pragma unroll
                for (int c = 0; c < 8; c++)
                    acc[r][c] = fmaf(ar[r], br[c], acc[r][c]);
        }
        __syncthreads();
    }
#pragma unroll
    for (int r = 0; r < 8; r++) {
        int grow = rb * 128 + ty * 8 + r;
        float* Crow = C + (size_t)grow * HID + cb * 128 + tx * 8;
#pragma unroll
        for (int c = 0; c < 8; c++)
            Crow[c] = acc[r][c];
    }
}

// ---------------- launch ------------------------------------------------------
extern "C" void kernel_launch(void* const* d_in, const int* in_sizes, int n_in,
                              void* d_out, int out_size)
{
    const float* hidden = (const float*)d_in[0];
    const float* cosb   = (const float*)d_in[1];
    const float* sinb   = (const float*)d_in[2];
    // d_in[3] = attention_mask (causal; computed analytically, unused)
    const float* Wq = (const float*)d_in[4];
    const float* bq = (const float*)d_in[5];
    const float* Wk = (const float*)d_in[6];
    const float* bk = (const float*)d_in[7];
    const float* Wv = (const float*)d_in[8];
    const float* bv = (const float*)d_in[9];
    const float* Wo = (const float*)d_in[10];
    float* out = (float*)d_out;

    qkv_gemm<<<dim3(24, 16), 256>>>(hidden, Wq, bq, Wk, bk, Wv, bv);
    rope_kernel<<<(S_LEN * QKV_N + 255) / 256, 256>>>(cosb, sinb);
    scores_gemm<<<dim3(16, 16, NH), 256>>>();
    zero_colsum<<<(NH * S_LEN + 255) / 256, 256>>>();
    row_softmax_colsum_kernel<<<dim3(S_LEN, NH), 256>>>();
    topk_kernel<<<NH, 256>>>();
    attn_v_kernel<<<dim3(S_LEN, NH), 128>>>();
    out_gemm<<<dim3(16, 16), 256>>>(Wo, out);
}

// round 13
// speedup vs baseline: 1.0014x; 1.0014x over previous
#include <cuda_runtime.h>
#include <math.h>

#define S_LEN   2048
#define HID     2048
#define NH      16
#define NKV     4
#define HD      128
#define HEAVY   204
#define RECENT  204
#define QKV_N   3072
#define SCALE   0.08838834764831845f   // 1/sqrt(128)

// ---------------- scratch (__device__ globals; no allocation allowed) -------
__device__ float g_qkv[S_LEN * QKV_N];                    // [s][3072] q|k|v pre-rope
__device__ float g_q[NH * S_LEN * HD];                    // [h][s][d] post-rope
__device__ float g_k[NKV * S_LEN * HD];                   // [kv][s][d] post-rope
__device__ float g_v[NKV * S_LEN * HD];                   // [kv][s][d]
__device__ float g_scores[(size_t)NH * S_LEN * S_LEN];    // [h][i][j], lower triangle valid
__device__ float g_rowmax[NH * S_LEN];
__device__ float g_colsum[NH * S_LEN];
__device__ int   g_heavy[NH * HEAVY];
__device__ float g_attn[S_LEN * HID];                     // [i][h*128+d]

// ---------------- fused QKV projection: hidden @ {Wq,Wk,Wv} + bias ----------
// 128x128 tile, BK=8, 256 threads, 8x8 per thread.
__global__ void __launch_bounds__(256) qkv_gemm(
    const float* __restrict__ A,
    const float* __restrict__ Wq, const float* __restrict__ bq,
    const float* __restrict__ Wk, const float* __restrict__ bk,
    const float* __restrict__ Wv, const float* __restrict__ bv)
{
    __shared__ float As[8][128];
    __shared__ float Bs[8][128];

    int cb = blockIdx.x;               // 0..23 (16 q-blocks, 4 k, 4 v)
    int rb = blockIdx.y;               // 0..15
    const float* W; const float* bias; int ldw; int ncol0;
    if (cb < 16)      { W = Wq; bias = bq; ldw = 2048; ncol0 = cb * 128; }
    else if (cb < 20) { W = Wk; bias = bk; ldw = 512;  ncol0 = (cb - 16) * 128; }
    else              { W = Wv; bias = bv; ldw = 512;  ncol0 = (cb - 20) * 128; }

    int tid  = threadIdx.x;
    int aRow = tid >> 1;               // 0..127
    int aCol = (tid & 1) * 4;          // 0 or 4
    int bRow = tid >> 5;               // 0..7
    int bCol = (tid & 31) * 4;         // 0..124
    int tx = tid & 15, ty = tid >> 4;

    const float* Ab = A + (size_t)(rb * 128 + aRow) * 2048 + aCol;
    const float* Bb = W + (size_t)bRow * ldw + ncol0 + bCol;

    float acc[8][8];
#pragma unroll
    for (int r = 0; r < 8; r++)
#pragma unroll
        for (int c = 0; c < 8; c++) acc[r][c] = 0.f;

    for (int k0 = 0; k0 < 2048; k0 += 8) {
        float4 a4 = *(const float4*)(Ab + k0);
        As[aCol + 0][aRow] = a4.x;
        As[aCol + 1][aRow] = a4.y;
        As[aCol + 2][aRow] = a4.z;
        As[aCol + 3][aRow] = a4.w;
        float4 b4 = *(const float4*)(Bb + (size_t)k0 * ldw);
        *(float4*)&Bs[bRow][bCol] = b4;
        __syncthreads();
#pragma unroll
        for (int kk = 0; kk < 8; kk++) {
            float4 a0 = *(const float4*)&As[kk][ty * 8];
            float4 a1 = *(const float4*)&As[kk][ty * 8 + 4];
            float4 b0 = *(const float4*)&Bs[kk][tx * 8];
            float4 b1 = *(const float4*)&Bs[kk][tx * 8 + 4];
            float ar[8] = {a0.x, a0.y, a0.z, a0.w, a1.x, a1.y, a1.z, a1.w};
            float br[8] = {b0.x, b0.y, b0.z, b0.w, b1.x, b1.y, b1.z, b1.w};
#pragma unroll
            for (int r = 0; r < 8; r++)
#pragma unroll
                for (int c = 0; c < 8; c++)
                    acc[r][c] = fmaf(ar[r], br[c], acc[r][c]);
        }
        __syncthreads();
    }
#pragma unroll
    for (int r = 0; r < 8; r++) {
        int grow = rb * 128 + ty * 8 + r;
        float* Crow = g_qkv + (size_t)grow * QKV_N + cb * 128 + tx * 8;
#pragma unroll
        for (int c = 0; c < 8; c++)
            Crow[c] = acc[r][c] + bias[ncol0 + tx * 8 + c];
    }
}

// ---------------- RoPE + split into head-major layouts ----------------------
__global__ void rope_kernel(const float* __restrict__ cosb,
                            const float* __restrict__ sinb)
{
    int idx = blockIdx.x * 256 + threadIdx.x;
    if (idx >= S_LEN * QKV_N) return;
    int s = idx / QKV_N;
    int c = idx % QKV_N;
    float x = g_qkv[idx];
    if (c < 2048) {                              // Q heads
        int h = c >> 7, d = c & 127;
        float cs = cosb[s * HD + d], sn = sinb[s * HD + d];
        float rot = (d < 64) ? -g_qkv[(size_t)s * QKV_N + c + 64]
                             :  g_qkv[(size_t)s * QKV_N + c - 64];
        g_q[((size_t)h * S_LEN + s) * HD + d] = x * cs + rot * sn;
    } else if (c < 2560) {                       // K heads
        int kc = c - 2048;
        int kv = kc >> 7, d = kc & 127;
        float cs = cosb[s * HD + d], sn = sinb[s * HD + d];
        float rot = (d < 64) ? -g_qkv[(size_t)s * QKV_N + c + 64]
                             :  g_qkv[(size_t)s * QKV_N + c - 64];
        g_k[((size_t)kv * S_LEN + s) * HD + d] = x * cs + rot * sn;
    } else {                                     // V heads (no rope)
        int vc = c - 2560;
        int kv = vc >> 7, d = vc & 127;
        g_v[((size_t)kv * S_LEN + s) * HD + d] = x;
    }
}

// ---------------- scores = scale * q @ k^T (lower-triangle tiles only) ------
__global__ void __launch_bounds__(256) scores_gemm()
{
    int jt = blockIdx.x, it = blockIdx.y, h = blockIdx.z;
    if (jt > it) return;

    __shared__ float As[8][128];
    __shared__ float Bs[8][128];

    const float* Q  = g_q + (size_t)h * S_LEN * HD;
    const float* Kk = g_k + (size_t)(h >> 2) * S_LEN * HD;

    int tid  = threadIdx.x;
    int aRow = tid >> 1;
    int aCol = (tid & 1) * 4;
    int tx = tid & 15, ty = tid >> 4;

    const float* Ab = Q  + (size_t)(it * 128 + aRow) * HD + aCol;
    const float* Bb = Kk + (size_t)(jt * 128 + aRow) * HD + aCol;

    float acc[8][8];
#pragma unroll
    for (int r = 0; r < 8; r++)
#pragma unroll
        for (int c = 0; c < 8; c++) acc[r][c] = 0.f;

    for (int k0 = 0; k0 < HD; k0 += 8) {
        float4 a4 = *(const float4*)(Ab + k0);
        As[aCol + 0][aRow] = a4.x;
        As[aCol + 1][aRow] = a4.y;
        As[aCol + 2][aRow] = a4.z;
        As[aCol + 3][aRow] = a4.w;
        float4 b4 = *(const float4*)(Bb + k0);
        Bs[aCol + 0][aRow] = b4.x;
        Bs[aCol + 1][aRow] = b4.y;
        Bs[aCol + 2][aRow] = b4.z;
        Bs[aCol + 3][aRow] = b4.w;
        __syncthreads();
#pragma unroll
        for (int kk = 0; kk < 8; kk++) {
            float4 a0 = *(const float4*)&As[kk][ty * 8];
            float4 a1 = *(const float4*)&As[kk][ty * 8 + 4];
            float4 b0 = *(const float4*)&Bs[kk][tx * 8];
            float4 b1 = *(const float4*)&Bs[kk][tx * 8 + 4];
            float ar[8] = {a0.x, a0.y, a0.z, a0.w, a1.x, a1.y, a1.z, a1.w};
            float br[8] = {b0.x, b0.y, b0.z, b0.w, b1.x, b1.y, b1.z, b1.w};
#pragma unroll
            for (int r = 0; r < 8; r++)
#pragma unroll
                for (int c = 0; c < 8; c++)
                    acc[r][c] = fmaf(ar[r], br[c], acc[r][c]);
        }
        __syncthreads();
    }
#pragma unroll
    for (int r = 0; r < 8; r++) {
        size_t row = (size_t)h * S_LEN + it * 128 + ty * 8 + r;
        float* Crow = g_scores + row * S_LEN + jt * 128 + tx * 8;
#pragma unroll
        for (int c = 0; c < 8; c++)
            Crow[c] = acc[r][c] * SCALE;
    }
}

// ---------------- zero colsum ------------------------------------------------
__global__ void zero_colsum()
{
    int idx = blockIdx.x * 256 + threadIdx.x;
    if (idx < NH * S_LEN) g_colsum[idx] = 0.f;
}

// ---------------- per-row softmax stats + colsum accumulation ---------------
// One block per (i, h). Causal: only j <= i valid.
__global__ void __launch_bounds__(256) row_softmax_colsum_kernel()
{
    int i = blockIdx.x, h = blockIdx.y;
    int tid = threadIdx.x;
    const float* srow = g_scores + ((size_t)h * S_LEN + i) * S_LEN;
    int L = i + 1;

    __shared__ float sh[S_LEN];
    __shared__ float red[256];

    float mloc = -3.4e38f;
    for (int j = tid; j < L; j += 256) {
        float v = srow[j];
        sh[j] = v;
        mloc = fmaxf(mloc, v);
    }
    red[tid] = mloc;
    __syncthreads();
    for (int s2 = 128; s2 > 0; s2 >>= 1) {
        if (tid < s2) red[tid] = fmaxf(red[tid], red[tid + s2]);
        __syncthreads();
    }
    float m = red[0];
    __syncthreads();

    float ssum = 0.f;
    for (int j = tid; j < L; j += 256) {
        float e = expf(sh[j] - m);
        sh[j] = e;
        ssum += e;
    }
    red[tid] = ssum;
    __syncthreads();
    for (int s2 = 128; s2 > 0; s2 >>= 1) {
        if (tid < s2) red[tid] += red[tid + s2];
        __syncthreads();
    }
    float inv = 1.0f / red[0];
    if (tid == 0) g_rowmax[h * S_LEN + i] = m;

    for (int j = tid; j < L; j += 256)
        atomicAdd(&g_colsum[h * S_LEN + j], sh[j] * inv);
}

// ---------------- per-head top-k (iterative argmax, lower-index tiebreak) ---
__global__ void __launch_bounds__(256) topk_kernel()
{
    int h = blockIdx.x;
    int tid = threadIdx.x;
    __shared__ float vals[S_LEN];
    __shared__ float rv[256];
    __shared__ int   ri[256];

    for (int j = tid; j < S_LEN; j += 256) vals[j] = g_colsum[h * S_LEN + j];
    __syncthreads();

    for (int t = 0; t < HEAVY; t++) {
        float bv = -3.4e38f; int bi = S_LEN;
        for (int j = tid; j < S_LEN; j += 256) {
            float v = vals[j];
            if (v > bv || (v == bv && j < bi)) { bv = v; bi = j; }
        }
        rv[tid] = bv; ri[tid] = bi;
        __syncthreads();
        for (int s2 = 128; s2 > 0; s2 >>= 1) {
            if (tid < s2) {
                float v2 = rv[tid + s2]; int i2 = ri[tid + s2];
                if (v2 > rv[tid] || (v2 == rv[tid] && i2 < ri[tid])) {
                    rv[tid] = v2; ri[tid] = i2;
                }
            }
            __syncthreads();
        }
        if (tid == 0) {
            int sel = ri[0];
            g_heavy[h * HEAVY + t] = sel;
            vals[sel] = -3.4e38f;
        }
        __syncthreads();
    }
}

// ---------------- masked softmax * V (sparse over kept columns) -------------
// keep(j) = |i-j|<=RECENT (causal => j in [i-RECENT, i])  OR  heavy j with j < i-RECENT.
// Uses full-row max m_i (kept-max <= m_i, ratios unchanged).
__global__ void __launch_bounds__(128) attn_v_kernel()
{
    int i = blockIdx.x, h = blockIdx.y;
    int d = threadIdx.x;                 // 0..127
    int kv = h >> 2;

    const float* srow = g_scores + ((size_t)h * S_LEN + i) * S_LEN;
    const float* V = g_v + (size_t)kv * S_LEN * HD;
    float m = g_rowmax[h * S_LEN + i];

    __shared__ float w[128];
    __shared__ int   jidx[128];

    float acc = 0.f, wsum = 0.f;

    // recent band: j in [max(0, i-RECENT), i]
    int rlo = i - RECENT; if (rlo < 0) rlo = 0;
    for (int base = rlo; base <= i; base += 128) {
        int cnt = i - base + 1; if (cnt > 128) cnt = 128;
        if (d < cnt) w[d] = expf(srow[base + d] - m);
        __syncthreads();
        for (int t = 0; t < cnt; t++) {
            float ww = w[t];
            wsum += ww;
            acc = fmaf(ww, V[(size_t)(base + t) * HD + d], acc);
        }
        __syncthreads();
    }

    // heavy-only columns: j < i - RECENT
    int cutoff = i - RECENT;
    for (int base = 0; base < HEAVY; base += 128) {
        int cnt = HEAVY - base; if (cnt > 128) cnt = 128;
        if (d < cnt) {
            int j = g_heavy[h * HEAVY + base + d];
            if (j < cutoff) { jidx[d] = j; w[d] = expf(srow[j] - m); }
            else            { jidx[d] = -1; w[d] = 0.f; }
        }
        __syncthreads();
        for (int t = 0; t < cnt; t++) {
            int j = jidx[t];
            if (j >= 0) {
                float ww = w[t];
                wsum += ww;
                acc = fmaf(ww, V[(size_t)j * HD + d], acc);
            }
        }
        __syncthreads();
    }

    g_attn[(size_t)i * HID + h * HD + d] = acc / wsum;
}

// ---------------- output projection: attn @ Wo -------------------------------
__global__ void __launch_bounds__(256) out_gemm(const float* __restrict__ W,
                                                float* __restrict__ C)
{
    __shared__ float As[8][128];
    __shared__ float Bs[8][128];

    int cb = blockIdx.x, rb = blockIdx.y;
    int tid  = threadIdx.x;
    int aRow = tid >> 1;
    int aCol = (tid & 1) * 4;
    int bRow = tid >> 5;
    int bCol = (tid & 31) * 4;
    int tx = tid & 15, ty = tid >> 4;

    const float* Ab = g_attn + (size_t)(rb * 128 + aRow) * HID + aCol;
    const float* Bb = W + (size_t)bRow * HID + cb * 128 + bCol;

    float acc[8][8];
#pragma unroll
    for (int r = 0; r < 8; r++)
#pragma unroll
        for (int c = 0; c < 8; c++) acc[r][c] = 0.f;

    for (int k0 = 0; k0 < HID; k0 += 8) {
        float4 a4 = *(const float4*)(Ab + k0);
        As[aCol + 0][aRow] = a4.x;
        As[aCol + 1][aRow] = a4.y;
        As[aCol + 2][aRow] = a4.z;
        As[aCol + 3][aRow] = a4.w;
        float4 b4 = *(const float4*)(Bb + (size_t)k0 * HID);
        *(float4*)&Bs[bRow][bCol] = b4;
        __syncthreads();
#pragma unroll
        for (int kk = 0; kk < 8; kk++) {
            float4 a0 = *(const float4*)&As[kk][ty * 8];
            float4 a1 = *(const float4*)&As[kk][ty * 8 + 4];
            float4 b0 = *(const float4*)&Bs[kk][tx * 8];
            float4 b1 = *(const float4*)&Bs[kk][tx * 8 + 4];
            float ar[8] = {a0.x, a0.y, a0.z, a0.w, a1.x, a1.y, a1.z, a1.w};
            float br[8] = {b0.x, b0.y, b0.z, b0.w, b1.x, b1.y, b1.z, b1.w};
#pragma unroll
            for (int r = 0; r < 8; r++)
#pragma unroll
                for (int c = 0; c < 8; c++)
                    acc[r][c] = fmaf(ar[r], br[c], acc[r][c]);
        }
        __syncthreads();
    }
#pragma unroll
    for (int r = 0; r < 8; r++) {
        int grow = rb * 128 + ty * 8 + r;
        float* Crow = C + (size_t)grow * HID + cb * 128 + tx * 8;
#pragma unroll
        for (int c = 0; c < 8; c++)
            Crow[c] = acc[r][c];
    }
}

// ---------------- launch ------------------------------------------------------
extern "C" void kernel_launch(void* const* d_in, const int* in_sizes, int n_in,
                              void* d_out, int out_size)
{
    const float* hidden = (const float*)d_in[0];
    const float* cosb   = (const float*)d_in[1];
    const float* sinb   = (const float*)d_in[2];
    // d_in[3] = attention_mask (causal; computed analytically, unused)
    const float* Wq = (const float*)d_in[4];
    const float* bq = (const float*)d_in[5];
    const float* Wk = (const float*)d_in[6];
    const float* bk = (const float*)d_in[7];
    const float* Wv = (const float*)d_in[8];
    const float* bv = (const float*)d_in[9];
    const float* Wo = (const float*)d_in[10];
    float* out = (float*)d_out;

    qkv_gemm<<<dim3(24, 16), 256>>>(hidden, Wq, bq, Wk, bk, Wv, bv);
    rope_kernel<<<(S_LEN * QKV_N + 255) / 256, 256>>>(cosb, sinb);
    scores_gemm<<<dim3(16, 16, NH), 256>>>();
    zero_colsum<<<(NH * S_LEN + 255) / 256, 256>>>();
    row_softmax_colsum_kernel<<<dim3(S_LEN, NH), 256>>>();
    topk_kernel<<<NH, 256>>>();
    attn_v_kernel<<<dim3(S_LEN, NH), 128>>>();
    out_gemm<<<dim3(16, 16), 256>>>(Wo, out);
}